// round 10
// baseline (speedup 1.0000x reference)
#include <cuda_runtime.h>
#include <cstdint>

// GriddingReverse: grid [B,128,128,128] fp32 -> ptcloud [B, 128^3, 3] fp32.
//
// Round-10: R9 (TMA store drain) hit 26.7us; ncu shows issue-bound (62.6%
// issue, nothing saturated, ~258 instr/warp). Cut instructions + load
// wavefronts: each warp now computes TWO adjacent output rows (y, y+1),
// sharing the middle input rows -> 6 LDG.128 per 2 rows instead of 8,
// 6 shfl instead of 8, index/boundary overhead amortized 2x.
//   - block = 8 warps = 16 consecutive (b,x,y) rows
//   - all 6 loads issued up front (MLP=6)
//   - results staged to smem (48B-stride STS.128), one 24KB cp.async.bulk

#define S 128
#define EPSF 1e-6f

__device__ __forceinline__ void zero_row(float4* s, int t)
{
    const float4 z4 = make_float4(0.f, 0.f, 0.f, 0.f);
    s[t * 3 + 0] = z4;
    s[t * 3 + 1] = z4;
    s[t * 3 + 2] = z4;
}

// Compute one output row from its 4 corner input rows.
// B00=(x-1,y-1) B01=(x-1,y) B10=(x,y-1) B11=(x,y); aXX = lane t-1's .w of BXX.
__device__ __forceinline__ void compute_row(
    float4 B00, float4 B01, float4 B10, float4 B11,
    float a00, float a01, float a10, float a11,
    float xf, float yf, float zf0, int t, float4* s)
{
    const float hi00[4] = {B00.x, B00.y, B00.z, B00.w};
    const float hi01[4] = {B01.x, B01.y, B01.z, B01.w};
    const float hi10[4] = {B10.x, B10.y, B10.z, B10.w};
    const float hi11[4] = {B11.x, B11.y, B11.z, B11.w};
    const float lo00[4] = {a00, B00.x, B00.y, B00.z};
    const float lo01[4] = {a01, B01.x, B01.y, B01.z};
    const float lo10[4] = {a10, B10.x, B10.y, B10.z};
    const float lo11[4] = {a11, B11.x, B11.y, B11.z};

    const float scale = 2.0f / (float)S;     // 0.015625
    const float half = (float)S * 0.5f;      // 64
    const float xm = xf - 1.0f;
    const float ym = yf - 1.0f;

    float res[12];

#pragma unroll
    for (int j = 0; j < 4; ++j) {
        const float p00 = lo00[j] + hi00[j];
        const float p01 = lo01[j] + hi01[j];
        const float p10 = lo10[j] + hi10[j];
        const float p11 = lo11[j] + hi11[j];

        const float x_lo = p00 + p01;               // dx = 0 rows
        const float x_hi = p10 + p11;               // dx = 1 rows
        const float y_lo = p00 + p10;               // dy = 0
        const float y_hi = p01 + p11;               // dy = 1
        const float z_lo = (lo00[j] + lo01[j]) + (lo10[j] + lo11[j]);
        const float z_hi = (hi00[j] + hi01[j]) + (hi10[j] + hi11[j]);

        const float wsum = x_lo + x_hi + EPSF;
        const float inv = __fdividef(1.0f, wsum);

        const float zf = zf0 + (float)j;

        float px = ((x_hi * xf + x_lo * xm) * inv - half) * scale;
        float py = ((y_hi * yf + y_lo * ym) * inv - half) * scale;
        float pz = ((z_hi * zf + z_lo * (zf - 1.0f)) * inv - half) * scale;

        if (t == 0 && j == 0) { px = 0.f; py = 0.f; pz = 0.f; }  // z==0

        res[j * 3 + 0] = px;
        res[j * 3 + 1] = py;
        res[j * 3 + 2] = pz;
    }

    s[t * 3 + 0] = make_float4(res[0], res[1],  res[2],  res[3]);
    s[t * 3 + 1] = make_float4(res[4], res[5],  res[6],  res[7]);
    s[t * 3 + 2] = make_float4(res[8], res[9],  res[10], res[11]);
}

__global__ void __launch_bounds__(256)
gridding_reverse_kernel(const float4* __restrict__ g4,
                        float4* __restrict__ out4)
{
    __shared__ __align__(16) float4 stage[1536];  // 16 rows * 96 float4 = 24KB

    const int tid = threadIdx.x;
    const int t   = tid & 31;                     // lane == z-group (4 points)
    const int wid = tid >> 5;
    const int w2  = blockIdx.x * 8 + wid;         // row-pair id

    const int y0 = (w2 & 63) << 1;                // even y of the pair
    const int x  = (w2 >> 6) & (S - 1);
    const int b  = w2 >> 13;

    float4* s = &stage[wid * 192];

    if (x == 0) {
        zero_row(s, t);
        zero_row(s + 96, t);
    } else {
        const int ym1 = (y0 == 0) ? 0 : (y0 - 1);   // clamped; row y0 zeroed anyway

        // row base (b, X, Y) in float4 units = ((b*S + X)*S + Y)*32
        const int gx0 = ((b * S + (x - 1)) * S) * 32 + t;   // X = x-1
        const int gx1 = gx0 + S * 32;                       // X = x

        const float4 A0 = g4[gx0 + ym1 * 32];       // (x-1, y-1)
        const float4 A1 = g4[gx0 + y0 * 32];        // (x-1, y  )
        const float4 A2 = g4[gx0 + (y0 + 1) * 32];  // (x-1, y+1)
        const float4 C0 = g4[gx1 + ym1 * 32];       // (x  , y-1)
        const float4 C1 = g4[gx1 + y0 * 32];        // (x  , y  )
        const float4 C2 = g4[gx1 + (y0 + 1) * 32];  // (x  , y+1)

        const float aA0 = __shfl_up_sync(0xffffffffu, A0.w, 1);
        const float aA1 = __shfl_up_sync(0xffffffffu, A1.w, 1);
        const float aA2 = __shfl_up_sync(0xffffffffu, A2.w, 1);
        const float aC0 = __shfl_up_sync(0xffffffffu, C0.w, 1);
        const float aC1 = __shfl_up_sync(0xffffffffu, C1.w, 1);
        const float aC2 = __shfl_up_sync(0xffffffffu, C2.w, 1);

        const float xf  = (float)x;
        const float zf0 = (float)(t * 4);

        if (y0 == 0) {
            zero_row(s, t);                          // y==0 boundary row
        } else {
            compute_row(A0, A1, C0, C1, aA0, aA1, aC0, aC1,
                        xf, (float)y0, zf0, t, s);
        }
        compute_row(A1, A2, C1, C2, aA1, aA2, aC1, aC2,
                    xf, (float)(y0 + 1), zf0, t, s + 96);
    }

    __syncthreads();

    // one bulk async copy: 24KB smem -> contiguous 24KB of output
    if (tid == 0) {
        float4* dst = out4 + (size_t)blockIdx.x * 1536;
        unsigned int smem_addr;
        asm("{ .reg .u64 a; cvta.to.shared.u64 a, %1; cvt.u32.u64 %0, a; }"
            : "=r"(smem_addr) : "l"(stage));
        asm volatile("fence.proxy.async.shared::cta;" ::: "memory");
        asm volatile(
            "cp.async.bulk.global.shared::cta.bulk_group [%0], [%1], %2;"
            :: "l"(dst), "r"(smem_addr), "r"(24576) : "memory");
        asm volatile("cp.async.bulk.commit_group;" ::: "memory");
        asm volatile("cp.async.bulk.wait_group 0;" ::: "memory");
    }
}

extern "C" void kernel_launch(void* const* d_in, const int* in_sizes, int n_in,
                              void* d_out, int out_size)
{
    const float4* g4 = (const float4*)d_in[0];
    float4* o4 = (float4*)d_out;

    const int total = in_sizes[0];          // B * 128^3
    const int nb = total >> 21;             // B
    const int npairs = nb * S * (S / 2);    // one warp per row pair
    const int blocks = npairs / 8;          // 8 pairs per 256-thread block

    gridding_reverse_kernel<<<blocks, 256>>>(g4, o4);
}

// round 11
// speedup vs baseline: 1.0132x; 1.0132x over previous
#include <cuda_runtime.h>
#include <cstdint>

// GriddingReverse: grid [B,128,128,128] fp32 -> ptcloud [B, 128^3, 3] fp32.
//
// Round-11: R10's row-pair kernel improved ncu-kernel time 24.0->21.95us but
// bench wall stayed ~27us; occ fell to 43% (regs 48) and the replay-steady-
// state L2 churn penalty grew. Keep row-pair + TMA drain; recover occupancy
// and cut FADDs:
//   - algebraic rewrite: hi*c + lo*(c-1) = s8*c - lo with s8 = 8-corner sum
//     (shared across x/y/z) -> 12 adds/point instead of 16, fewer live regs
//   - __launch_bounds__(256, 6): 6 CTAs/SM (75% theoretical occ)
//   - block = 8 warps = 16 rows; 6 LDG.128 per warp (MLP=6), shfl z-neighbor
//   - stage to smem, one 24KB cp.async.bulk drain

#define S 128
#define EPSF 1e-6f

__device__ __forceinline__ void zero_row(float4* s, int t)
{
    const float4 z4 = make_float4(0.f, 0.f, 0.f, 0.f);
    s[t * 3 + 0] = z4;
    s[t * 3 + 1] = z4;
    s[t * 3 + 2] = z4;
}

// Compute one output row from its 4 corner input rows.
// B00=(x-1,y-1) B01=(x-1,y) B10=(x,y-1) B11=(x,y); aXX = lane t-1's .w of BXX.
__device__ __forceinline__ void compute_row(
    float4 B00, float4 B01, float4 B10, float4 B11,
    float a00, float a01, float a10, float a11,
    float xf, float yf, float zf0, int t, float4* s)
{
    const float hi00[4] = {B00.x, B00.y, B00.z, B00.w};
    const float hi01[4] = {B01.x, B01.y, B01.z, B01.w};
    const float hi10[4] = {B10.x, B10.y, B10.z, B10.w};
    const float hi11[4] = {B11.x, B11.y, B11.z, B11.w};
    const float lo00[4] = {a00, B00.x, B00.y, B00.z};
    const float lo01[4] = {a01, B01.x, B01.y, B01.z};
    const float lo10[4] = {a10, B10.x, B10.y, B10.z};
    const float lo11[4] = {a11, B11.x, B11.y, B11.z};

    const float scale = 2.0f / (float)S;     // 0.015625
    const float half = (float)S * 0.5f;      // 64

    float res[12];

#pragma unroll
    for (int j = 0; j < 4; ++j) {
        const float p00 = lo00[j] + hi00[j];
        const float p01 = lo01[j] + hi01[j];
        const float p10 = lo10[j] + hi10[j];
        const float p11 = lo11[j] + hi11[j];

        const float x_lo = p00 + p01;                     // dx = 0 corners
        const float x_hi = p10 + p11;                     // dx = 1 corners
        const float s8   = x_lo + x_hi;                   // all 8 corners
        const float y_lo = p00 + p10;                     // dy = 0
        const float z_lo = (lo00[j] + lo01[j]) + (lo10[j] + lo11[j]);

        const float inv = __fdividef(1.0f, s8 + EPSF);
        const float zf = zf0 + (float)j;

        // hi*c + lo*(c-1) == s8*c - lo
        float px = (fmaf(s8, xf, -x_lo) * inv - half) * scale;
        float py = (fmaf(s8, yf, -y_lo) * inv - half) * scale;
        float pz = (fmaf(s8, zf, -z_lo) * inv - half) * scale;

        if (t == 0 && j == 0) { px = 0.f; py = 0.f; pz = 0.f; }  // z==0

        res[j * 3 + 0] = px;
        res[j * 3 + 1] = py;
        res[j * 3 + 2] = pz;
    }

    s[t * 3 + 0] = make_float4(res[0], res[1],  res[2],  res[3]);
    s[t * 3 + 1] = make_float4(res[4], res[5],  res[6],  res[7]);
    s[t * 3 + 2] = make_float4(res[8], res[9],  res[10], res[11]);
}

__global__ void __launch_bounds__(256, 6)
gridding_reverse_kernel(const float4* __restrict__ g4,
                        float4* __restrict__ out4)
{
    __shared__ __align__(16) float4 stage[1536];  // 16 rows * 96 float4 = 24KB

    const int tid = threadIdx.x;
    const int t   = tid & 31;                     // lane == z-group (4 points)
    const int wid = tid >> 5;
    const int w2  = blockIdx.x * 8 + wid;         // row-pair id

    const int y0 = (w2 & 63) << 1;                // even y of the pair
    const int x  = (w2 >> 6) & (S - 1);
    const int b  = w2 >> 13;

    float4* s = &stage[wid * 192];

    if (x == 0) {
        zero_row(s, t);
        zero_row(s + 96, t);
    } else {
        const int ym1 = (y0 == 0) ? 0 : (y0 - 1);   // clamped; row y0 zeroed anyway

        // row base (b, X, Y) in float4 units = ((b*S + X)*S + Y)*32
        const int gx0 = ((b * S + (x - 1)) * S) * 32 + t;   // X = x-1
        const int gx1 = gx0 + S * 32;                       // X = x

        const float4 A0 = g4[gx0 + ym1 * 32];       // (x-1, y-1)
        const float4 A1 = g4[gx0 + y0 * 32];        // (x-1, y  )
        const float4 A2 = g4[gx0 + (y0 + 1) * 32];  // (x-1, y+1)
        const float4 C0 = g4[gx1 + ym1 * 32];       // (x  , y-1)
        const float4 C1 = g4[gx1 + y0 * 32];        // (x  , y  )
        const float4 C2 = g4[gx1 + (y0 + 1) * 32];  // (x  , y+1)

        const float aA0 = __shfl_up_sync(0xffffffffu, A0.w, 1);
        const float aA1 = __shfl_up_sync(0xffffffffu, A1.w, 1);
        const float aA2 = __shfl_up_sync(0xffffffffu, A2.w, 1);
        const float aC0 = __shfl_up_sync(0xffffffffu, C0.w, 1);
        const float aC1 = __shfl_up_sync(0xffffffffu, C1.w, 1);
        const float aC2 = __shfl_up_sync(0xffffffffu, C2.w, 1);

        const float xf  = (float)x;
        const float zf0 = (float)(t * 4);

        if (y0 == 0) {
            zero_row(s, t);                          // y==0 boundary row
        } else {
            compute_row(A0, A1, C0, C1, aA0, aA1, aC0, aC1,
                        xf, (float)y0, zf0, t, s);
        }
        compute_row(A1, A2, C1, C2, aA1, aA2, aC1, aC2,
                    xf, (float)(y0 + 1), zf0, t, s + 96);
    }

    __syncthreads();

    // one bulk async copy: 24KB smem -> contiguous 24KB of output
    if (tid == 0) {
        float4* dst = out4 + (size_t)blockIdx.x * 1536;
        unsigned int smem_addr;
        asm("{ .reg .u64 a; cvta.to.shared.u64 a, %1; cvt.u32.u64 %0, a; }"
            : "=r"(smem_addr) : "l"(stage));
        asm volatile("fence.proxy.async.shared::cta;" ::: "memory");
        asm volatile(
            "cp.async.bulk.global.shared::cta.bulk_group [%0], [%1], %2;"
            :: "l"(dst), "r"(smem_addr), "r"(24576) : "memory");
        asm volatile("cp.async.bulk.commit_group;" ::: "memory");
        asm volatile("cp.async.bulk.wait_group 0;" ::: "memory");
    }
}

extern "C" void kernel_launch(void* const* d_in, const int* in_sizes, int n_in,
                              void* d_out, int out_size)
{
    const float4* g4 = (const float4*)d_in[0];
    float4* o4 = (float4*)d_out;

    const int total = in_sizes[0];          // B * 128^3
    const int nb = total >> 21;             // B
    const int npairs = nb * S * (S / 2);    // one warp per row pair
    const int blocks = npairs / 8;          // 8 pairs per 256-thread block

    gridding_reverse_kernel<<<blocks, 256>>>(g4, o4);
}

// round 13
// speedup vs baseline: 1.0920x; 1.0777x over previous
#include <cuda_runtime.h>
#include <cstdint>

// GriddingReverse: grid [B,128,128,128] fp32 -> ptcloud [B, 128^3, 3] fp32.
//
// Round-13: R12's theory (steady-state DRAM-bound: 100MB output writeback +
// 33MB input re-read per graph replay == the pinned ~26.7us bench wall)
// survives; its implementation didn't compile: sm_100 ptxas only encodes
// L2::evict_last on 256-bit loads. Keep the important half:
//   - TMA store drain tagged createpolicy evict_first + L2::cache_hint
//     (output is dead data -> preferred eviction victim; input then stays
//     L2-resident by plain LRU, no load-side hint needed)
//   - loads back to plain __ldg (LDG.E.NC.128)
// SM structure unchanged from R11 (row-pair, s8 rewrite, 24KB TMA drain).

#define S 128
#define EPSF 1e-6f

__device__ __forceinline__ void zero_row(float4* s, int t)
{
    const float4 z4 = make_float4(0.f, 0.f, 0.f, 0.f);
    s[t * 3 + 0] = z4;
    s[t * 3 + 1] = z4;
    s[t * 3 + 2] = z4;
}

// Compute one output row from its 4 corner input rows.
// B00=(x-1,y-1) B01=(x-1,y) B10=(x,y-1) B11=(x,y); aXX = lane t-1's .w of BXX.
__device__ __forceinline__ void compute_row(
    float4 B00, float4 B01, float4 B10, float4 B11,
    float a00, float a01, float a10, float a11,
    float xf, float yf, float zf0, int t, float4* s)
{
    const float hi00[4] = {B00.x, B00.y, B00.z, B00.w};
    const float hi01[4] = {B01.x, B01.y, B01.z, B01.w};
    const float hi10[4] = {B10.x, B10.y, B10.z, B10.w};
    const float hi11[4] = {B11.x, B11.y, B11.z, B11.w};
    const float lo00[4] = {a00, B00.x, B00.y, B00.z};
    const float lo01[4] = {a01, B01.x, B01.y, B01.z};
    const float lo10[4] = {a10, B10.x, B10.y, B10.z};
    const float lo11[4] = {a11, B11.x, B11.y, B11.z};

    const float scale = 2.0f / (float)S;     // 0.015625
    const float half = (float)S * 0.5f;      // 64

    float res[12];

#pragma unroll
    for (int j = 0; j < 4; ++j) {
        const float p00 = lo00[j] + hi00[j];
        const float p01 = lo01[j] + hi01[j];
        const float p10 = lo10[j] + hi10[j];
        const float p11 = lo11[j] + hi11[j];

        const float x_lo = p00 + p01;                     // dx = 0 corners
        const float x_hi = p10 + p11;                     // dx = 1 corners
        const float s8   = x_lo + x_hi;                   // all 8 corners
        const float y_lo = p00 + p10;                     // dy = 0
        const float z_lo = (lo00[j] + lo01[j]) + (lo10[j] + lo11[j]);

        const float inv = __fdividef(1.0f, s8 + EPSF);
        const float zf = zf0 + (float)j;

        // hi*c + lo*(c-1) == s8*c - lo
        float px = (fmaf(s8, xf, -x_lo) * inv - half) * scale;
        float py = (fmaf(s8, yf, -y_lo) * inv - half) * scale;
        float pz = (fmaf(s8, zf, -z_lo) * inv - half) * scale;

        if (t == 0 && j == 0) { px = 0.f; py = 0.f; pz = 0.f; }  // z==0

        res[j * 3 + 0] = px;
        res[j * 3 + 1] = py;
        res[j * 3 + 2] = pz;
    }

    s[t * 3 + 0] = make_float4(res[0], res[1],  res[2],  res[3]);
    s[t * 3 + 1] = make_float4(res[4], res[5],  res[6],  res[7]);
    s[t * 3 + 2] = make_float4(res[8], res[9],  res[10], res[11]);
}

__global__ void __launch_bounds__(256, 6)
gridding_reverse_kernel(const float4* __restrict__ g4,
                        float4* __restrict__ out4)
{
    __shared__ __align__(16) float4 stage[1536];  // 16 rows * 96 float4 = 24KB

    const int tid = threadIdx.x;
    const int t   = tid & 31;                     // lane == z-group (4 points)
    const int wid = tid >> 5;
    const int w2  = blockIdx.x * 8 + wid;         // row-pair id

    const int y0 = (w2 & 63) << 1;                // even y of the pair
    const int x  = (w2 >> 6) & (S - 1);
    const int b  = w2 >> 13;

    float4* s = &stage[wid * 192];

    if (x == 0) {
        zero_row(s, t);
        zero_row(s + 96, t);
    } else {
        const int ym1 = (y0 == 0) ? 0 : (y0 - 1);   // clamped; row y0 zeroed anyway

        // row base (b, X, Y) in float4 units = ((b*S + X)*S + Y)*32
        const int gx0 = ((b * S + (x - 1)) * S) * 32 + t;   // X = x-1
        const int gx1 = gx0 + S * 32;                       // X = x

        const float4 A0 = __ldg(g4 + gx0 + ym1 * 32);       // (x-1, y-1)
        const float4 A1 = __ldg(g4 + gx0 + y0 * 32);        // (x-1, y  )
        const float4 A2 = __ldg(g4 + gx0 + (y0 + 1) * 32);  // (x-1, y+1)
        const float4 C0 = __ldg(g4 + gx1 + ym1 * 32);       // (x  , y-1)
        const float4 C1 = __ldg(g4 + gx1 + y0 * 32);        // (x  , y  )
        const float4 C2 = __ldg(g4 + gx1 + (y0 + 1) * 32);  // (x  , y+1)

        const float aA0 = __shfl_up_sync(0xffffffffu, A0.w, 1);
        const float aA1 = __shfl_up_sync(0xffffffffu, A1.w, 1);
        const float aA2 = __shfl_up_sync(0xffffffffu, A2.w, 1);
        const float aC0 = __shfl_up_sync(0xffffffffu, C0.w, 1);
        const float aC1 = __shfl_up_sync(0xffffffffu, C1.w, 1);
        const float aC2 = __shfl_up_sync(0xffffffffu, C2.w, 1);

        const float xf  = (float)x;
        const float zf0 = (float)(t * 4);

        if (y0 == 0) {
            zero_row(s, t);                          // y==0 boundary row
        } else {
            compute_row(A0, A1, C0, C1, aA0, aA1, aC0, aC1,
                        xf, (float)y0, zf0, t, s);
        }
        compute_row(A1, A2, C1, C2, aA1, aA2, aC1, aC2,
                    xf, (float)(y0 + 1), zf0, t, s + 96);
    }

    __syncthreads();

    // one bulk async copy: 24KB smem -> contiguous 24KB of output,
    // tagged evict_first so dead output lines don't evict the live input.
    if (tid == 0) {
        float4* dst = out4 + (size_t)blockIdx.x * 1536;
        unsigned int smem_addr;
        asm("{ .reg .u64 a; cvta.to.shared.u64 a, %1; cvt.u32.u64 %0, a; }"
            : "=r"(smem_addr) : "l"(stage));
        unsigned long long pol;
        asm("createpolicy.fractional.L2::evict_first.b64 %0, 1.0;" : "=l"(pol));
        asm volatile("fence.proxy.async.shared::cta;" ::: "memory");
        asm volatile(
            "cp.async.bulk.global.shared::cta.bulk_group.L2::cache_hint "
            "[%0], [%1], %2, %3;"
            :: "l"(dst), "r"(smem_addr), "r"(24576), "l"(pol) : "memory");
        asm volatile("cp.async.bulk.commit_group;" ::: "memory");
        asm volatile("cp.async.bulk.wait_group 0;" ::: "memory");
    }
}

extern "C" void kernel_launch(void* const* d_in, const int* in_sizes, int n_in,
                              void* d_out, int out_size)
{
    const float4* g4 = (const float4*)d_in[0];
    float4* o4 = (float4*)d_out;

    const int total = in_sizes[0];          // B * 128^3
    const int nb = total >> 21;             // B
    const int npairs = nb * S * (S / 2);    // one warp per row pair
    const int blocks = npairs / 8;          // 8 pairs per 256-thread block

    gridding_reverse_kernel<<<blocks, 256>>>(g4, o4);
}

// round 14
// speedup vs baseline: 1.0962x; 1.0039x over previous
#include <cuda_runtime.h>
#include <cstdint>

// GriddingReverse: grid [B,128,128,128] fp32 -> ptcloud [B, 128^3, 3] fp32.
//
// Round-14: R13 (evict_first TMA drain) fixed the steady-state L2 pollution
// (bench 26.6->24.7, bench/ncu gap 4.2->1.6us). Now issue-bound again
// (54.6% issue, nothing saturated). Two instruction-count cuts:
//   1. epilogue folding: half*scale == 1.0 exactly, so
//      (num*inv - 64)/64 == fma(num, inv_s, -1) with inv_s = (1/64)/wsum.
//      4 ops/coordinate -> 2.
//   2. per-warp TMA drain: each warp's 3KB stage region is contiguous in
//      smem AND gmem -> lane 0 drains it; removes the block-wide
//      __syncthreads, warps retire independently.
// Unchanged: row-pair per warp, 6 LDG.128 (MLP=6), shfl z-neighbor,
// evict_first policy on the bulk store.

#define S 128
#define EPSF 1e-6f

__device__ __forceinline__ void zero_row(float4* s, int t)
{
    const float4 z4 = make_float4(0.f, 0.f, 0.f, 0.f);
    s[t * 3 + 0] = z4;
    s[t * 3 + 1] = z4;
    s[t * 3 + 2] = z4;
}

// Compute one output row from its 4 corner input rows.
// B00=(x-1,y-1) B01=(x-1,y) B10=(x,y-1) B11=(x,y); aXX = lane t-1's .w of BXX.
__device__ __forceinline__ void compute_row(
    float4 B00, float4 B01, float4 B10, float4 B11,
    float a00, float a01, float a10, float a11,
    float xf, float yf, float zf0, int t, float4* s)
{
    const float hi00[4] = {B00.x, B00.y, B00.z, B00.w};
    const float hi01[4] = {B01.x, B01.y, B01.z, B01.w};
    const float hi10[4] = {B10.x, B10.y, B10.z, B10.w};
    const float hi11[4] = {B11.x, B11.y, B11.z, B11.w};
    const float lo00[4] = {a00, B00.x, B00.y, B00.z};
    const float lo01[4] = {a01, B01.x, B01.y, B01.z};
    const float lo10[4] = {a10, B10.x, B10.y, B10.z};
    const float lo11[4] = {a11, B11.x, B11.y, B11.z};

    float res[12];

#pragma unroll
    for (int j = 0; j < 4; ++j) {
        const float p00 = lo00[j] + hi00[j];
        const float p01 = lo01[j] + hi01[j];
        const float p10 = lo10[j] + hi10[j];
        const float p11 = lo11[j] + hi11[j];

        const float x_lo = p00 + p01;                     // dx = 0 corners
        const float x_hi = p10 + p11;                     // dx = 1 corners
        const float s8   = x_lo + x_hi;                   // all 8 corners
        const float y_lo = p00 + p10;                     // dy = 0
        const float z_lo = (lo00[j] + lo01[j]) + (lo10[j] + lo11[j]);

        // (num/wsum - 64) * (1/64) == fma(num, (1/64)/wsum, -1)   [64*(1/64)==1]
        const float inv_s = __fdividef(0.015625f, s8 + EPSF);
        const float zf = zf0 + (float)j;

        // hi*c + lo*(c-1) == s8*c - lo
        float px = fmaf(fmaf(s8, xf, -x_lo), inv_s, -1.0f);
        float py = fmaf(fmaf(s8, yf, -y_lo), inv_s, -1.0f);
        float pz = fmaf(fmaf(s8, zf, -z_lo), inv_s, -1.0f);

        if (t == 0 && j == 0) { px = 0.f; py = 0.f; pz = 0.f; }  // z==0

        res[j * 3 + 0] = px;
        res[j * 3 + 1] = py;
        res[j * 3 + 2] = pz;
    }

    s[t * 3 + 0] = make_float4(res[0], res[1],  res[2],  res[3]);
    s[t * 3 + 1] = make_float4(res[4], res[5],  res[6],  res[7]);
    s[t * 3 + 2] = make_float4(res[8], res[9],  res[10], res[11]);
}

__global__ void __launch_bounds__(256, 6)
gridding_reverse_kernel(const float4* __restrict__ g4,
                        float4* __restrict__ out4)
{
    __shared__ __align__(16) float4 stage[1536];  // 16 rows * 96 float4 = 24KB

    const int tid = threadIdx.x;
    const int t   = tid & 31;                     // lane == z-group (4 points)
    const int wid = tid >> 5;
    const int w2  = blockIdx.x * 8 + wid;         // row-pair id

    const int y0 = (w2 & 63) << 1;                // even y of the pair
    const int x  = (w2 >> 6) & (S - 1);
    const int b  = w2 >> 13;

    float4* s = &stage[wid * 192];

    if (x == 0) {
        zero_row(s, t);
        zero_row(s + 96, t);
    } else {
        const int ym1 = (y0 == 0) ? 0 : (y0 - 1);   // clamped; row y0 zeroed anyway

        // row base (b, X, Y) in float4 units = ((b*S + X)*S + Y)*32
        const int gx0 = ((b * S + (x - 1)) * S) * 32 + t;   // X = x-1
        const int gx1 = gx0 + S * 32;                       // X = x

        const float4 A0 = __ldg(g4 + gx0 + ym1 * 32);       // (x-1, y-1)
        const float4 A1 = __ldg(g4 + gx0 + y0 * 32);        // (x-1, y  )
        const float4 A2 = __ldg(g4 + gx0 + (y0 + 1) * 32);  // (x-1, y+1)
        const float4 C0 = __ldg(g4 + gx1 + ym1 * 32);       // (x  , y-1)
        const float4 C1 = __ldg(g4 + gx1 + y0 * 32);        // (x  , y  )
        const float4 C2 = __ldg(g4 + gx1 + (y0 + 1) * 32);  // (x  , y+1)

        const float aA0 = __shfl_up_sync(0xffffffffu, A0.w, 1);
        const float aA1 = __shfl_up_sync(0xffffffffu, A1.w, 1);
        const float aA2 = __shfl_up_sync(0xffffffffu, A2.w, 1);
        const float aC0 = __shfl_up_sync(0xffffffffu, C0.w, 1);
        const float aC1 = __shfl_up_sync(0xffffffffu, C1.w, 1);
        const float aC2 = __shfl_up_sync(0xffffffffu, C2.w, 1);

        const float xf  = (float)x;
        const float zf0 = (float)(t * 4);

        if (y0 == 0) {
            zero_row(s, t);                          // y==0 boundary row
        } else {
            compute_row(A0, A1, C0, C1, aA0, aA1, aC0, aC1,
                        xf, (float)y0, zf0, t, s);
        }
        compute_row(A1, A2, C1, C2, aA1, aA2, aC1, aC2,
                    xf, (float)(y0 + 1), zf0, t, s + 96);
    }

    // per-warp drain: this warp's 3KB stage region -> contiguous 3KB of out,
    // tagged evict_first so dead output lines don't evict the live input.
    __syncwarp();
    if (t == 0) {
        float4* dst = out4 + (size_t)blockIdx.x * 1536 + wid * 192;
        unsigned int smem_addr;
        asm("{ .reg .u64 a; cvta.to.shared.u64 a, %1; cvt.u32.u64 %0, a; }"
            : "=r"(smem_addr) : "l"(s));
        unsigned long long pol;
        asm("createpolicy.fractional.L2::evict_first.b64 %0, 1.0;" : "=l"(pol));
        asm volatile("fence.proxy.async.shared::cta;" ::: "memory");
        asm volatile(
            "cp.async.bulk.global.shared::cta.bulk_group.L2::cache_hint "
            "[%0], [%1], %2, %3;"
            :: "l"(dst), "r"(smem_addr), "r"(3072), "l"(pol) : "memory");
        asm volatile("cp.async.bulk.commit_group;" ::: "memory");
        asm volatile("cp.async.bulk.wait_group 0;" ::: "memory");
    }
}

extern "C" void kernel_launch(void* const* d_in, const int* in_sizes, int n_in,
                              void* d_out, int out_size)
{
    const float4* g4 = (const float4*)d_in[0];
    float4* o4 = (float4*)d_out;

    const int total = in_sizes[0];          // B * 128^3
    const int nb = total >> 21;             // B
    const int npairs = nb * S * (S / 2);    // one warp per row pair
    const int blocks = npairs / 8;          // 8 pairs per 256-thread block

    gridding_reverse_kernel<<<blocks, 256>>>(g4, o4);
}